// round 16
// baseline (speedup 1.0000x reference)
#include <cuda_runtime.h>
#include <cuda_fp16.h>
#include <cstdint>

#define F_ 32
#define B_ 4096
#define D_ 64
#define K_ 512
#define NTHREADS 256
#define NTILES 1024
#define NCTAS 456
#define PREP_UNITS 512

// ---------------- device scratch ----------------
__device__ __half g_wh1[(size_t)F_ * K_ * D_];  // fp16 limb1, [f][k][d]
__device__ __half g_wh2[(size_t)F_ * K_ * D_];  // fp16 limb2, [f][k][d]
__device__ float  g_wn [F_ * K_];               // 0.5*||w_k||^2
__device__ float  g_partial[NTILES];            // per-TILE loss partials
__device__ int    g_count;
__device__ int    g_tile;
__device__ int    g_sync;

__device__ __forceinline__ uint32_t smem_u32(const void* p) {
    uint32_t a;
    asm("{ .reg .u64 t; cvta.to.shared.u64 t, %1; cvt.u32.u64 %0, t; }"
        : "=r"(a) : "l"(p));
    return a;
}

#define LDSM_X4(r_, addr_) \
    asm volatile("ldmatrix.sync.aligned.m8n8.x4.shared.b16 {%0,%1,%2,%3}, [%4];" \
        : "=r"((r_)[0]), "=r"((r_)[1]), "=r"((r_)[2]), "=r"((r_)[3]) : "r"(addr_))

#define CP_ASYNC16(dst_, src_) \
    asm volatile("cp.async.cg.shared.global [%0], [%1], 16;" :: "r"(dst_), "l"(src_))
#define CP_COMMIT() asm volatile("cp.async.commit_group;" ::: "memory")
#define CP_WAIT0()  asm volatile("cp.async.wait_group 0;" ::: "memory")

__device__ __forceinline__ void mma_f16(float* c, const uint32_t* a,
                                        const uint32_t* b) {
    asm volatile(
        "mma.sync.aligned.m16n8k16.row.col.f32.f16.f16.f32 "
        "{%0,%1,%2,%3}, {%4,%5,%6,%7}, {%8,%9}, {%0,%1,%2,%3};"
        : "+f"(c[0]), "+f"(c[1]), "+f"(c[2]), "+f"(c[3])
        : "r"(a[0]), "r"(a[1]), "r"(a[2]), "r"(a[3]), "r"(b[0]), "r"(b[1]));
}

__device__ __forceinline__ uint32_t pack_h2(__half a, __half b) {
    __half2 h = __halves2half2(a, b);
    return *(uint32_t*)&h;
}

// smem (bytes). 128B rows + SW128 XOR swizzle: phys = row*128 + (col ^ ((row&7)<<4))
#define OFF_WNS  0
#define OFF_SIDX 2048
#define OFF_RED8 2560
#define OFF_TILE 2592      // s_t broadcast
#define OFF_X1   4096
#define OFF_X2   20480
#define OFF_WS   36864
#define SMEM_BYTES 69632

// ---------------------------------------------------------------------------
// Fused kernel: phase 0 = cooperative prep (transpose + fp16 limb split +
// norms) + grid-wide sync; phase 1 = persistent tile loop (R15 GEMM).
// ---------------------------------------------------------------------------
__global__ __launch_bounds__(NTHREADS, 3)
void vq_main(const float* __restrict__ x, const float* __restrict__ w,
             float* __restrict__ out, int loss_pos) {
    extern __shared__ __align__(1024) char smem[];
    const uint32_t sb = smem_u32(smem);
    float* wns  = (float*)(smem + OFF_WNS);
    int*   sidx = (int*)(smem + OFF_SIDX);
    float* red8 = (float*)(smem + OFF_RED8);
    int*   s_t  = (int*)(smem + OFF_TILE);
    float* red_v = (float*)(smem + OFF_WS);
    int*   red_i = (int*)(smem + OFF_WS + 8192);
    // prep-phase overlays (X region is unused during phase 0)
    float (*ts)[65] = (float(*)[65])(smem + OFF_X1);          // 32x65 floats
    float (*ps)[9]  = (float(*)[9])(smem + OFF_X1 + 8448);    // 32x9 floats

    const int tid = threadIdx.x;
    const int wid = tid >> 5;
    const int lane = tid & 31;
    const int tq = lane >> 2, tr = lane & 3;
    const int wm = wid >> 2,  wn = wid & 3;
    const int lq = lane & 7,  quad = lane >> 3;
    const uint32_t xorv = (uint32_t)lq << 4;

    // ================= phase 0: cooperative prep =================
    for (int u = blockIdx.x; u < PREP_UNITS; u += NCTAS) {
        const int f = u >> 4, kt = u & 15;       // 32 codes per unit
        const float* wf = w + (size_t)f * D_ * K_ + kt * 32;

        __syncthreads();
        for (int i = tid; i < 64 * 32; i += NTHREADS) {
            int d = i >> 5, kk = i & 31;
            ts[kk][d] = wf[(size_t)d * K_ + kk];   // coalesced along k
        }
        __syncthreads();

        size_t base = ((size_t)f * K_ + (size_t)kt * 32) * D_;
        for (int i = tid; i < 32 * 64; i += NTHREADS) {
            int kk = i >> 6, d = i & 63;
            float v = ts[kk][d];
            __half h1 = __float2half_rn(v);
            __half h2 = __float2half_rn(v - __half2float(h1));
            g_wh1[base + i] = h1;
            g_wh2[base + i] = h2;
        }
        {
            int kk = tid >> 3, seg = tid & 7;
            float s = 0.f;
#pragma unroll
            for (int d8 = 0; d8 < 8; ++d8) {
                float v = ts[kk][seg * 8 + d8];
                s += v * v;
            }
            ps[kk][seg] = s;
        }
        __syncthreads();
        if (tid < 32) {
            float s = 0.f;
#pragma unroll
            for (int g = 0; g < 8; ++g) s += ps[tid][g];
            g_wn[f * K_ + kt * 32 + tid] = 0.5f * s;
        }
    }

    // grid-wide sync (all 456 CTAs are resident: occ 3 x 152 SMs)
    __syncthreads();
    if (tid == 0) {
        __threadfence();
        atomicAdd(&g_sync, 1);
        while (atomicAdd(&g_sync, 0) < NCTAS) { __nanosleep(64); }
        *s_t = 0;
    }
    __syncthreads();

    // ================= phase 1: persistent tile loop =================
    for (;;) {
        __syncthreads();    // fence prior epilogue smem reads & s_t reuse
        if (tid == 0) *s_t = atomicAdd(&g_tile, 1);
        __syncthreads();
        const int t = *s_t;
        if (t >= NTILES) break;

        const int f  = t >> 5;
        const int b0 = (t & 31) * 128;
        const __half* wh1g = g_wh1 + ((size_t)f << 9) * D_;
        const __half* wh2g = g_wh2 + ((size_t)f << 9) * D_;

        // ---- prefetch chunk 0 (codes 0..63, both limbs) into buf 0 ----
#pragma unroll
        for (int tt = 0; tt < 4; ++tt) {
            int i = tid + tt * 256;             // [0,1024)
            int limb = i >> 9;
            int n    = (i >> 3) & 63;
            int ch   = i & 7;
            uint32_t dst = sb + OFF_WS + (uint32_t)limb * 8192
                         + (uint32_t)n * 128
                         + (((uint32_t)ch * 16) ^ ((uint32_t)(n & 7) << 4));
            const __half* src = (limb ? wh2g : wh1g) + (size_t)n * 64 + ch * 8;
            CP_ASYNC16(dst, src);
        }
        CP_COMMIT();

        wns[tid]       = g_wn[(f << 9) + tid];
        wns[tid + 256] = g_wn[(f << 9) + tid + 256];

        // ---- x tile -> fp16 limbs, swizzled 128B rows ----
        const float* xg = x + ((size_t)f * B_ + b0) * D_;
#pragma unroll
        for (int tt = 0; tt < 8; ++tt) {
            int i = tid + tt * 256;             // [0,2048)
            int r = i >> 4, c4 = i & 15;
            float4 v = ((const float4*)(xg + (size_t)r * D_))[c4];
            __half h1[4], h2[4];
            float vv[4] = {v.x, v.y, v.z, v.w};
#pragma unroll
            for (int j = 0; j < 4; ++j) {
                h1[j] = __float2half_rn(vv[j]);
                h2[j] = __float2half_rn(vv[j] - __half2float(h1[j]));
            }
            uint32_t off = (uint32_t)r * 128
                         + (((uint32_t)c4 * 8) ^ ((uint32_t)(r & 7) << 4));
            *(uint2*)(smem + OFF_X1 + off) =
                make_uint2(pack_h2(h1[0], h1[1]), pack_h2(h1[2], h1[3]));
            *(uint2*)(smem + OFF_X2 + off) =
                make_uint2(pack_h2(h2[0], h2[1]), pack_h2(h2[2], h2[3]));
        }

        float best[8];
        int   bidx[8];
#pragma unroll
        for (int i = 0; i < 8; ++i) { best[i] = -1e30f; bidx[i] = 0; }

        const uint32_t aBase = sb + OFF_X1
            + (uint32_t)(wm * 64 + lq + ((quad & 1) << 3)) * 128;
        const uint32_t aColBase = (uint32_t)((quad >> 1) << 4);
        const uint32_t bRowOff = (uint32_t)(wn * 16 + lq) * 128;
        const uint32_t bColBase = (uint32_t)quad * 16;

        for (int c = 0; c < 8; ++c) {
            CP_WAIT0();
            __syncthreads();

            if (c < 7) {
                int cn = c + 1;
                uint32_t bufoff = (uint32_t)(cn & 1) * 16384;
#pragma unroll
                for (int tt = 0; tt < 4; ++tt) {
                    int i = tid + tt * 256;
                    int limb = i >> 9;
                    int n    = (i >> 3) & 63;
                    int ch   = i & 7;
                    uint32_t dst = sb + OFF_WS + bufoff + (uint32_t)limb * 8192
                                 + (uint32_t)n * 128
                                 + (((uint32_t)ch * 16) ^ ((uint32_t)(n & 7) << 4));
                    const __half* src = (limb ? wh2g : wh1g)
                                      + ((size_t)(cn * 64 + n)) * 64 + ch * 8;
                    CP_ASYNC16(dst, src);
                }
                CP_COMMIT();
            }

            const uint32_t wsb = sb + OFF_WS + (uint32_t)(c & 1) * 16384;

            float acc[4][2][4];
#pragma unroll
            for (int i = 0; i < 4; ++i)
#pragma unroll
                for (int j = 0; j < 2; ++j)
#pragma unroll
                    for (int q = 0; q < 4; ++q) acc[i][j][q] = 0.f;

#pragma unroll
            for (int kkp = 0; kkp < 2; ++kkp) {
                uint32_t bb1[2][4], bb2[2][4];
#pragma unroll
                for (int j = 0; j < 2; ++j) {
                    uint32_t ba = wsb + bRowOff + (uint32_t)j * 1024
                                + ((bColBase + (uint32_t)kkp * 64) ^ xorv);
                    LDSM_X4(bb1[j], ba);
                    LDSM_X4(bb2[j], ba + 8192);
                }
#pragma unroll
                for (int kk2 = 0; kk2 < 2; ++kk2) {
                    const int kreg = kk2 * 2;
                    const uint32_t kcol = (uint32_t)(kkp * 2 + kk2) * 32;
                    uint32_t a1[4][4], a2[4][4];
#pragma unroll
                    for (int i = 0; i < 4; ++i) {
                        uint32_t aa = aBase + (uint32_t)i * 2048
                                    + ((aColBase + kcol) ^ xorv);
                        LDSM_X4(a1[i], aa);
                        LDSM_X4(a2[i], aa + 16384);
                    }
#pragma unroll
                    for (int i = 0; i < 4; ++i)
#pragma unroll
                        for (int j = 0; j < 2; ++j)
                            mma_f16(acc[i][j], a1[i], &bb1[j][kreg]);  // h1*w1
#pragma unroll
                    for (int i = 0; i < 4; ++i)
#pragma unroll
                        for (int j = 0; j < 2; ++j)
                            mma_f16(acc[i][j], a1[i], &bb2[j][kreg]);  // h1*w2
#pragma unroll
                    for (int i = 0; i < 4; ++i)
#pragma unroll
                        for (int j = 0; j < 2; ++j)
                            mma_f16(acc[i][j], a2[i], &bb1[j][kreg]);  // h2*w1
                }
            }

            // fold chunk scores into running argmax (k ascending; strict >)
#pragma unroll
            for (int j = 0; j < 2; ++j)
#pragma unroll
                for (int c01 = 0; c01 < 2; ++c01) {
                    int kg = c * 64 + wn * 16 + j * 8 + tr * 2 + c01;
                    float wnv = wns[kg];
#pragma unroll
                    for (int i = 0; i < 4; ++i)
#pragma unroll
                        for (int h = 0; h < 2; ++h) {
                            float s = acc[i][j][h * 2 + c01] - wnv;
                            int slot = i * 2 + h;
                            if (s > best[slot]) { best[slot] = s; bidx[slot] = kg; }
                        }
                }
        }

        __syncthreads();   // ws reads done; overlay reduction arrays

#pragma unroll
        for (int i = 0; i < 4; ++i)
#pragma unroll
            for (int h = 0; h < 2; ++h) {
                int row = wm * 64 + i * 16 + h * 8 + tq;
                red_v[row * 16 + wn * 4 + tr] = best[i * 2 + h];
                red_i[row * 16 + wn * 4 + tr] = bidx[i * 2 + h];
            }
        __syncthreads();

        if (tid < 128) {
            float bv = -1e30f;
            int bk = 0x7FFFFFFF;
#pragma unroll
            for (int t2 = 0; t2 < 16; ++t2) {
                float v = red_v[tid * 16 + t2];
                int  kk = red_i[tid * 16 + t2];
                if (v > bv || (v == bv && kk < bk)) { bv = v; bk = kk; }
            }
            sidx[tid] = bk;
        }
        __syncthreads();

        // ---- gather (q = h1 + h2) + loss ----
        float lsum = 0.f;
        float* og = out + ((size_t)f * B_ + b0) * D_;
        for (int e = tid; e < 128 * D_; e += NTHREADS) {
            int r = e >> 6, d = e & 63;
            size_t gi = (size_t)sidx[r] * D_ + d;
            float q  = __half2float(wh1g[gi]) + __half2float(wh2g[gi]);
            float xv = xg[e];
            og[e] = q;
            float dif = q - xv;
            lsum += dif * dif;
        }
#pragma unroll
        for (int o = 16; o > 0; o >>= 1)
            lsum += __shfl_xor_sync(0xFFFFFFFFu, lsum, o);
        if ((tid & 31) == 0) red8[wid] = lsum;
        __syncthreads();
        if (tid == 0) {
            float tt = 0.f;
#pragma unroll
            for (int i = 0; i < 8; ++i) tt += red8[i];
            g_partial[t] = tt;   // tile-indexed -> deterministic final sum
        }
    }

    // ---- all tiles done: last CTA reduces loss, resets counters ----
    __shared__ int s_last;
    if (tid == 0) {
        __threadfence();
        int old = atomicAdd(&g_count, 1);
        s_last = (old == NCTAS - 1) ? 1 : 0;
    }
    __syncthreads();

    if (s_last) {
        float s = 0.f;
#pragma unroll
        for (int tt = 0; tt < NTILES / NTHREADS; ++tt)
            s += g_partial[tid + tt * NTHREADS];
#pragma unroll
        for (int o = 16; o > 0; o >>= 1)
            s += __shfl_xor_sync(0xFFFFFFFFu, s, o);
        if ((tid & 31) == 0) red8[wid] = s;
        __syncthreads();
        if (tid == 0) {
            float tt = 0.f;
#pragma unroll
            for (int i = 0; i < 8; ++i) tt += red8[i];
            out[loss_pos] = tt * (1.25f / (float)(F_ * B_ * D_));
            g_count = 0;
            g_tile  = 0;
            g_sync  = 0;     // reset for next graph replay
        }
    }
}

// ---------------------------------------------------------------------------
extern "C" void kernel_launch(void* const* d_in, const int* in_sizes, int n_in,
                              void* d_out, int out_size) {
    const float* x = (const float*)d_in[0];   // (F,B,D)
    const float* w = (const float*)d_in[1];   // (F,D,K)
    float* out = (float*)d_out;

    cudaFuncSetAttribute(vq_main, cudaFuncAttributeMaxDynamicSharedMemorySize,
                         SMEM_BYTES);

    vq_main<<<NCTAS, NTHREADS, SMEM_BYTES>>>(x, w, out, out_size - 1);
}